// round 14
// baseline (speedup 1.0000x reference)
#include <cuda_runtime.h>

// CrimeModelLSTM: 2-layer LSTM (H=8), B=4096, T=512, FC head [4,8].
// R14: layer-per-warp (R9 decomposition) with 4-STEP BARRIER GROUPS.
//   CTA = 64 threads = warp A (layer-1 engine) + warp B (layer-2 engine),
//   4 elements per CTA, 1024 CTAs (all resident in one wave @ 7 CTAs/SM).
//   A, group t (steps 4t..4t+3): per step: L1 gates+acts -> h1o; store dup to
//     slot ring; broadcast h1 via shfl; Pa = bb2 + wi2[.,0:4]*h1 -> slot ring.
//     After 4 steps: bar.sync(64).
//   B, group t: bar.sync(64); per step: LDS Pa + h1-hi dups; += wi2[.,4:8]*h1hi
//     + wh2*h2; acts -> h2o; broadcast h2 via shfl (h2 never leaves B).
//   8-slot rings, group parity selects slot half -> race-free under the group
//   barrier (A reuses a half only after B has passed the next barrier).
//   R9's failure was 512 per-step barriers (CPI 8.9 at 49 instr); 128 barriers
//   amortize to ~12 cyc/step.
// Kept: fma.rn.f32x2 gate-pair packing, tanh.approx activations, (1+tanh)
// cell algebra with h carried as 2h (0.5 folded into consumer weights).

typedef unsigned long long u64;

__device__ __forceinline__ u64 pk2(float lo, float hi) {
    u64 r; asm("mov.b64 %0, {%1,%2};" : "=l"(r) : "f"(lo), "f"(hi)); return r;
}
__device__ __forceinline__ void upk(u64 v, float& lo, float& hi) {
    asm("mov.b64 {%0,%1}, %2;" : "=f"(lo), "=f"(hi) : "l"(v));
}
__device__ __forceinline__ u64 fma2(u64 a, u64 b, u64 c) {
    u64 d; asm("fma.rn.f32x2 %0, %1, %2, %3;" : "=l"(d) : "l"(a), "l"(b), "l"(c)); return d;
}
__device__ __forceinline__ float tanhap(float x) {
    float r; asm("tanh.approx.f32 %0, %1;" : "=f"(r) : "f"(x)); return r;
}
#define PAIR_BAR() asm volatile("bar.sync 1, 64;" ::: "memory")

__global__ void __launch_bounds__(64, 7)
lstm2_kernel(const float* __restrict__ x,
             const float* __restrict__ Wih1, const float* __restrict__ Whh1,
             const float* __restrict__ bih1, const float* __restrict__ bhh1,
             const float* __restrict__ Wih2, const float* __restrict__ Whh2,
             const float* __restrict__ bih2, const float* __restrict__ bhh2,
             const float* __restrict__ Wfc,  const float* __restrict__ bfc,
             float* __restrict__ out)
{
    constexpr int T = 512;
    constexpr int H = 8;
    constexpr int NG = T / 4;     // 128 groups

    const int warp = threadIdx.x >> 5;   // 0 = A (layer 1), 1 = B (layer 2)
    const int lane = threadIdx.x & 31;
    const int grp  = lane >> 3;          // element within CTA (0..3)
    const int j    = lane & 7;           // hidden unit owned
    const int e    = blockIdx.x * 4 + grp;

    // 8-slot rings: [slot][grp][unit]
    __shared__ alignas(16) u64        sh1[8][4][8];   // h1 dup-pairs (2h1,2h1)
    __shared__ alignas(16) ulonglong2 sPa[8][4][8];   // L2 partial (pair0,pair1)

    // gate scales (i,f,g,o): sigmoid rows fold 0.5; tanh row 1.0
    const float gsc[4] = {0.5f, 0.5f, 1.0f, 0.5f};

    if (warp == 0) {
        // ================= Warp A: layer-1 engine =================
        u64 wx1p[2], bb1p[2], bb2p[2], wh1p[2][H], wi2lo[2][4];
        #pragma unroll
        for (int p = 0; p < 2; p++) {
            const int gA = 2 * p, gB = 2 * p + 1;
            const int rA = gA * 8 + j, rB = gB * 8 + j;
            const float sA = gsc[gA], sB = gsc[gB];
            wx1p[p] = pk2(Wih1[rA] * sA, Wih1[rB] * sB);
            bb1p[p] = pk2((bih1[rA] + bhh1[rA]) * sA, (bih1[rB] + bhh1[rB]) * sB);
            bb2p[p] = pk2((bih2[rA] + bhh2[rA]) * sA, (bih2[rB] + bhh2[rB]) * sB);
            #pragma unroll
            for (int k = 0; k < H; k++)      // h1 carried as 2h -> extra 0.5
                wh1p[p][k] = pk2(Whh1[rA * H + k] * sA * 0.5f,
                                 Whh1[rB * H + k] * sB * 0.5f);
            #pragma unroll
            for (int k = 0; k < 4; k++)
                wi2lo[p][k] = pk2(Wih2[rA * H + k] * sA * 0.5f,
                                  Wih2[rB * H + k] * sB * 0.5f);
        }

        u64 h1d[H];
        #pragma unroll
        for (int k = 0; k < H; k++) h1d[k] = 0ull;
        float c1 = 0.0f;

        const float4* __restrict__ xp4 =
            reinterpret_cast<const float4*>(x + (long)e * T);
        float4 xv = xp4[0];

        for (int t = 0; t < NG; ++t) {
            float4 xn = xp4[(t + 1 < NG) ? t + 1 : t];
            float xs[4] = {xv.x, xv.y, xv.z, xv.w};
            const int sb = (t & 1) * 4;          // slot half for this group
            #pragma unroll
            for (int q = 0; q < 4; ++q) {        // step s = 4t+q, slot sb+q
                u64 x2 = pk2(xs[q], xs[q]);
                u64 G0 = fma2(wx1p[0], x2, bb1p[0]);
                u64 G1 = fma2(wx1p[1], x2, bb1p[1]);
                #pragma unroll
                for (int k = 0; k < H; ++k) {
                    G0 = fma2(wh1p[0][k], h1d[k], G0);
                    G1 = fma2(wh1p[1][k], h1d[k], G1);
                }
                float a, b;
                upk(G0, a, b); const float ti = tanhap(a), tf = tanhap(b);
                upk(G1, a, b); const float tg = tanhap(a), to = tanhap(b);
                const float A = fmaf(ti, tg, tg);   // 2*i*g
                const float Z = fmaf(tf, c1, c1);   // 2*f*c
                c1 = (A + Z) * 0.5f;
                const float tc = tanhap(c1);
                const float h1o = fmaf(to, tc, tc); // = 2*h1
                sh1[sb + q][grp][j] = pk2(h1o, h1o);
                // broadcast h1(s) into register dup-pairs
                #pragma unroll
                for (int k = 0; k < H; ++k) {
                    const float v = __shfl_sync(0xffffffffu, h1o, k, 8);
                    h1d[k] = pk2(v, v);
                }
                // Pa(s) = bb2 + wi2[.,0:4] * h1(s)[0:4]
                u64 Pa0 = fma2(wi2lo[0][0], h1d[0], bb2p[0]);
                u64 Pa1 = fma2(wi2lo[1][0], h1d[0], bb2p[1]);
                #pragma unroll
                for (int k = 1; k < 4; ++k) {
                    Pa0 = fma2(wi2lo[0][k], h1d[k], Pa0);
                    Pa1 = fma2(wi2lo[1][k], h1d[k], Pa1);
                }
                sPa[sb + q][grp][j] = make_ulonglong2(Pa0, Pa1);
            }
            xv = xn;
            PAIR_BAR();                          // group t published
        }
    } else {
        // ================= Warp B: layer-2 engine =================
        u64 wi2hi[2][4], wh2p[2][H];
        #pragma unroll
        for (int p = 0; p < 2; p++) {
            const int gA = 2 * p, gB = 2 * p + 1;
            const int rA = gA * 8 + j, rB = gB * 8 + j;
            const float sA = gsc[gA], sB = gsc[gB];
            #pragma unroll
            for (int k = 0; k < 4; k++)
                wi2hi[p][k] = pk2(Wih2[rA * H + 4 + k] * sA * 0.5f,
                                  Wih2[rB * H + 4 + k] * sB * 0.5f);
            #pragma unroll
            for (int k = 0; k < H; k++)      // h2 carried as 2h
                wh2p[p][k] = pk2(Whh2[rA * H + k] * sA * 0.5f,
                                 Whh2[rB * H + k] * sB * 0.5f);
        }

        u64 h2d[H];
        #pragma unroll
        for (int k = 0; k < H; k++) h2d[k] = 0ull;
        float c2 = 0.0f;
        float h2o = 0.0f;

        for (int t = 0; t < NG; ++t) {
            PAIR_BAR();                          // wait for A's group t
            const int sb = (t & 1) * 4;
            #pragma unroll
            for (int q = 0; q < 4; ++q) {        // step s = 4t+q
                const ulonglong2 pa = sPa[sb + q][grp][j];
                const ulonglong2* rh =
                    reinterpret_cast<const ulonglong2*>(&sh1[sb + q][grp][4]);
                const ulonglong2 v0 = rh[0], v1 = rh[1];
                const u64 hh[4] = {v0.x, v0.y, v1.x, v1.y};

                u64 P0 = pa.x, P1 = pa.y;
                #pragma unroll
                for (int k = 0; k < 4; ++k) {
                    P0 = fma2(wi2hi[0][k], hh[k], P0);
                    P1 = fma2(wi2hi[1][k], hh[k], P1);
                }
                #pragma unroll
                for (int k = 0; k < H; ++k) {
                    P0 = fma2(wh2p[0][k], h2d[k], P0);
                    P1 = fma2(wh2p[1][k], h2d[k], P1);
                }
                float a, b;
                upk(P0, a, b); const float ti = tanhap(a), tf = tanhap(b);
                upk(P1, a, b); const float tg = tanhap(a), to = tanhap(b);
                const float A = fmaf(ti, tg, tg);
                const float Z = fmaf(tf, c2, c2);
                c2 = (A + Z) * 0.5f;
                const float tc = tanhap(c2);
                h2o = fmaf(to, tc, tc);          // = 2*h2
                #pragma unroll
                for (int k = 0; k < H; ++k) {
                    const float v = __shfl_sync(0xffffffffu, h2o, k, 8);
                    h2d[k] = pk2(v, v);
                }
            }
        }

        // ---- FC head: h2o (=2*h2(T-1)) lives on lane grp*8+k for unit k ----
        const int base = lane & 24;
        float hv[H];
        #pragma unroll
        for (int k = 0; k < H; k++)
            hv[k] = __shfl_sync(0xffffffffu, h2o, base + k);
        if (j < 4) {
            float acc = bfc[j];
            #pragma unroll
            for (int k = 0; k < H; k++)
                acc = fmaf(Wfc[j * H + k] * 0.5f, hv[k], acc);
            out[e * 4 + j] = acc;
        }
    }
}

extern "C" void kernel_launch(void* const* d_in, const int* in_sizes, int n_in,
                              void* d_out, int out_size)
{
    const float* x    = (const float*)d_in[0];
    const float* Wih1 = (const float*)d_in[1];
    const float* Whh1 = (const float*)d_in[2];
    const float* bih1 = (const float*)d_in[3];
    const float* bhh1 = (const float*)d_in[4];
    const float* Wih2 = (const float*)d_in[5];
    const float* Whh2 = (const float*)d_in[6];
    const float* bih2 = (const float*)d_in[7];
    const float* bhh2 = (const float*)d_in[8];
    const float* Wfc  = (const float*)d_in[9];
    const float* bfc  = (const float*)d_in[10];
    float* out = (float*)d_out;

    const int B = 4096;
    // 4 elements per CTA (A+B warp pair) -> 1024 CTAs, 2048 warps,
    // 7 CTAs/SM (forced by launch_bounds) -> single wave on 148 SMs.
    dim3 grid(B / 4), block(64);
    lstm2_kernel<<<grid, block>>>(x, Wih1, Whh1, bih1, bhh1,
                                  Wih2, Whh2, bih2, bhh2, Wfc, bfc, out);
}

// round 15
// speedup vs baseline: 1.1886x; 1.1886x over previous
#include <cuda_runtime.h>

// CrimeModelLSTM: 2-layer LSTM (H=8), B=4096, T=512, FC head [4,8].
// R15 = R3 core + overlap polish. Pipe model (fits all 14 rounds):
//   fma.rn.f32x2 rt=4/SMSP -> fp32 MAC floor = 346 cyc/step (93us); R3 = 82%.
// Changes: exact R3 geometry (1024 CTAs x 32), (1+tanh) cell algebra with h
// carried as 2h (0.5 folded into consumer weights), 8-STEP UNROLL for a wider
// ptxas scheduling window (interleave adjacent steps' FMA bursts with
// MUFU/SHFL phases), bias folded into first-FMA addends.

typedef unsigned long long u64;

__device__ __forceinline__ u64 pk2(float lo, float hi) {
    u64 r; asm("mov.b64 %0, {%1,%2};" : "=l"(r) : "f"(lo), "f"(hi)); return r;
}
__device__ __forceinline__ void upk(u64 v, float& lo, float& hi) {
    asm("mov.b64 {%0,%1}, %2;" : "=f"(lo), "=f"(hi) : "l"(v));
}
__device__ __forceinline__ u64 fma2(u64 a, u64 b, u64 c) {
    u64 d; asm("fma.rn.f32x2 %0, %1, %2, %3;" : "=l"(d) : "l"(a), "l"(b), "l"(c)); return d;
}
__device__ __forceinline__ float tanhap(float x) {
    float r; asm("tanh.approx.f32 %0, %1;" : "=f"(r) : "f"(x)); return r;
}

__global__ void __launch_bounds__(32)
lstm2_kernel(const float* __restrict__ x,
             const float* __restrict__ Wih1, const float* __restrict__ Whh1,
             const float* __restrict__ bih1, const float* __restrict__ bhh1,
             const float* __restrict__ Wih2, const float* __restrict__ Whh2,
             const float* __restrict__ bih2, const float* __restrict__ bhh2,
             const float* __restrict__ Wfc,  const float* __restrict__ bfc,
             float* __restrict__ out)
{
    constexpr int T = 512;
    constexpr int H = 8;

    const int tid = blockIdx.x * 32 + threadIdx.x;
    const int e   = tid >> 3;       // batch element
    const int j   = tid & 7;        // hidden unit owned by this thread

    // gate scales (i,f,g,o): sigmoid rows fold 0.5; tanh row 1.0
    const float gsc[4] = {0.5f, 0.5f, 1.0f, 0.5f};

    // ---- weights packed as gate pairs: pair0=(i,f), pair1=(g,o) ----
    // h carried as 2h -> extra 0.5 on all h-consuming weights
    u64 wh1p[2][H], wi2p[2][H], wh2p[2][H];
    u64 wx1p[2], bb1p[2], bb2p[2];
    #pragma unroll
    for (int p = 0; p < 2; p++) {
        const int gA = 2 * p, gB = 2 * p + 1;
        const int rA = gA * 8 + j, rB = gB * 8 + j;
        const float sA = gsc[gA], sB = gsc[gB];
        wx1p[p] = pk2(Wih1[rA] * sA, Wih1[rB] * sB);
        bb1p[p] = pk2((bih1[rA] + bhh1[rA]) * sA, (bih1[rB] + bhh1[rB]) * sB);
        bb2p[p] = pk2((bih2[rA] + bhh2[rA]) * sA, (bih2[rB] + bhh2[rB]) * sB);
        #pragma unroll
        for (int k = 0; k < H; k++) {
            wh1p[p][k] = pk2(Whh1[rA * H + k] * sA * 0.5f,
                             Whh1[rB * H + k] * sB * 0.5f);
            wi2p[p][k] = pk2(Wih2[rA * H + k] * sA * 0.5f,
                             Wih2[rB * H + k] * sB * 0.5f);
            wh2p[p][k] = pk2(Whh2[rA * H + k] * sA * 0.5f,
                             Whh2[rB * H + k] * sB * 0.5f);
        }
    }

    // ---- state: dup-pair operands (2h, 2h) ----
    u64 h1d[H], h2d[H];
    #pragma unroll
    for (int k = 0; k < H; k++) { h1d[k] = 0ull; h2d[k] = 0ull; }
    float c1 = 0.0f, c2 = 0.0f;

    const float4* __restrict__ xp = reinterpret_cast<const float4*>(x + (long)e * T);
    float4 va = xp[0];
    float4 vb = xp[1];

    // ---- prologue: L1 step 0 (h1 = 0: only x term) ----
    {
        u64 x2 = pk2(va.x, va.x);
        u64 P0 = fma2(wx1p[0], x2, bb1p[0]);
        u64 P1 = fma2(wx1p[1], x2, bb1p[1]);
        float a, b;
        upk(P0, a, b); const float ti = tanhap(a), tf = tanhap(b); (void)tf;
        upk(P1, a, b); const float tg = tanhap(a), to = tanhap(b);
        c1 = fmaf(ti, tg, tg) * 0.5f;          // (2ig)/2, c was 0
        const float tc = tanhap(c1);
        const float h1o = fmaf(to, tc, tc);    // = 2*h1
        #pragma unroll
        for (int k = 0; k < H; k++) {
            const float v = __shfl_sync(0xffffffffu, h1o, k, 8);
            h1d[k] = pk2(v, v);
        }
    }

    // ---- main loop: 8 steps/iter; body computes L2(t) and L1(t+1) ----
    for (int tt = 0; tt < T / 8; ++tt) {
        const int nxt = (tt + 1 < T / 8) ? (tt + 1) : tt;
        float4 vc = xp[2 * nxt];
        float4 vd = xp[2 * nxt + 1];
        // x for L1 steps t+1, t = 8*tt + q
        float xs[8] = {va.y, va.z, va.w, vb.x, vb.y, vb.z, vb.w, vc.x};

        #pragma unroll
        for (int q = 0; q < 8; q++) {
            u64 x2 = pk2(xs[q], xs[q]);
            u64 P1_0 = fma2(wx1p[0], x2, bb1p[0]);
            u64 P1_1 = fma2(wx1p[1], x2, bb1p[1]);
            // fold bb2 into the first wi2 FMA's addend
            u64 P2_0 = fma2(wi2p[0][0], h1d[0], bb2p[0]);
            u64 P2_1 = fma2(wi2p[1][0], h1d[0], bb2p[1]);
            P1_0 = fma2(wh1p[0][0], h1d[0], P1_0);
            P1_1 = fma2(wh1p[1][0], h1d[0], P1_1);
            #pragma unroll
            for (int k = 1; k < H; k++) {
                const u64 h = h1d[k];
                P2_0 = fma2(wi2p[0][k], h, P2_0);
                P2_1 = fma2(wi2p[1][k], h, P2_1);
                P1_0 = fma2(wh1p[0][k], h, P1_0);
                P1_1 = fma2(wh1p[1][k], h, P1_1);
            }
            #pragma unroll
            for (int k = 0; k < H; k++) {
                const u64 h = h2d[k];
                P2_0 = fma2(wh2p[0][k], h, P2_0);
                P2_1 = fma2(wh2p[1][k], h, P2_1);
            }

            float a, b;
            upk(P1_0, a, b); const float ti1 = tanhap(a), tf1 = tanhap(b);
            upk(P1_1, a, b); const float tg1 = tanhap(a), to1 = tanhap(b);
            upk(P2_0, a, b); const float ti2 = tanhap(a), tf2 = tanhap(b);
            upk(P2_1, a, b); const float tg2 = tanhap(a), to2 = tanhap(b);

            const float A1 = fmaf(ti1, tg1, tg1);   // 2*i*g
            const float Z1 = fmaf(tf1, c1, c1);     // 2*f*c
            const float A2 = fmaf(ti2, tg2, tg2);
            const float Z2 = fmaf(tf2, c2, c2);
            c1 = (A1 + Z1) * 0.5f;
            c2 = (A2 + Z2) * 0.5f;
            const float tc1 = tanhap(c1);
            const float tc2 = tanhap(c2);
            const float h1o = fmaf(to1, tc1, tc1);  // = 2*h1
            const float h2o = fmaf(to2, tc2, tc2);  // = 2*h2

            #pragma unroll
            for (int k = 0; k < H; k++) {
                const float v1 = __shfl_sync(0xffffffffu, h1o, k, 8);
                const float v2 = __shfl_sync(0xffffffffu, h2o, k, 8);
                h1d[k] = pk2(v1, v1);
                h2d[k] = pk2(v2, v2);
            }
        }
        va = vc;
        vb = vd;
    }
    // loop produced h2 = 2*h2(T-1) in h2d; final (extra) L1 result unused.

    // ---- FC head: h2d[k].lo = 2*h2(T-1)[k]; fold the 0.5 into Wfc ----
    if (j < 4) {
        float acc = bfc[j];
        #pragma unroll
        for (int k = 0; k < H; k++) {
            float lo, hi;
            upk(h2d[k], lo, hi); (void)hi;
            acc = fmaf(Wfc[j * H + k] * 0.5f, lo, acc);
        }
        out[e * 4 + j] = acc;
    }
}

extern "C" void kernel_launch(void* const* d_in, const int* in_sizes, int n_in,
                              void* d_out, int out_size)
{
    const float* x    = (const float*)d_in[0];
    const float* Wih1 = (const float*)d_in[1];
    const float* Whh1 = (const float*)d_in[2];
    const float* bih1 = (const float*)d_in[3];
    const float* bhh1 = (const float*)d_in[4];
    const float* Wih2 = (const float*)d_in[5];
    const float* Whh2 = (const float*)d_in[6];
    const float* bih2 = (const float*)d_in[7];
    const float* bhh2 = (const float*)d_in[8];
    const float* Wfc  = (const float*)d_in[9];
    const float* bfc  = (const float*)d_in[10];
    float* out = (float*)d_out;

    const int B = 4096;
    // R3 geometry (best measured): 8 threads/element, 32-thread CTAs.
    dim3 grid(B * 8 / 32), block(32);
    lstm2_kernel<<<grid, block>>>(x, Wih1, Whh1, bih1, bhh1,
                                  Wih2, Whh2, bih2, bhh2, Wfc, bfc, out);
}